// round 7
// baseline (speedup 1.0000x reference)
#include <cuda_runtime.h>
#include <cuda_bf16.h>

// DET_PROB hierarchical cumprod expansion — v5:
//   4 rows/block, 8 chunks/thread, all streaming loads front-batched (MLP=8).
// B0=8, B1=16, B2=16 -> 2048 leaves/row, 128 leaf-groups of 16.
//
// Phase 0: each thread issues its 8 dc2 float4 loads (.cs) back-to-back.
// Phase 1: 256 threads compute 512 prefixes (4 rows x 128 groups, 2 each)
//          into smem — latency hidden under the in-flight streaming loads.
// Phase 2: 4-lane segmented shfl scan per chunk, scale by prefix, store (.cs).

#define B0 8
#define B1 16
#define B2 16
#define GROUPS 128                         // leaf groups per row
#define ROW_ELEMS 2048                     // B0*B1*B2
#define ROW_CHUNKS 512                     // float4 chunks per row
#define ROWS_PER_BLK 4
#define BLK_CHUNKS (ROW_CHUNKS * ROWS_PER_BLK)   // 2048
#define BLOCK 256
#define CPT 8                              // chunks per thread

__global__ __launch_bounds__(BLOCK) void det_prob_kernel(
    const float* __restrict__ dc0,
    const float* __restrict__ dc1,
    const float* __restrict__ dc2,
    float* __restrict__ out)
{
    __shared__ float pfx[GROUPS * ROWS_PER_BLK];   // 512 prefixes

    int tid = threadIdx.x;
    size_t blk_base = (size_t)blockIdx.x * BLK_CHUNKS;   // float4 units

    // ---------- Phase 0: front-batch all 8 streaming loads ----------
    const float4* src = (const float4*)dc2;
    float4 xs[CPT];
#pragma unroll
    for (int it = 0; it < CPT; it++)
        xs[it] = __ldcs(&src[blk_base + tid + it * BLOCK]);

    // ---------- Phase 1: two prefixes per thread (overlaps loads) ----------
#pragma unroll
    for (int j = 0; j < 2; j++) {
        int idx = tid + j * BLOCK;        // 0..511 prefix index
        int r   = idx >> 7;               // row within block (0..3)
        int g   = idx & 127;              // group within row
        int a0  = g >> 4;
        int a1  = g & 15;
        size_t row = (size_t)blockIdx.x * ROWS_PER_BLK + r;

        // c0 = cumprod(dc0[row])[a0]
        const float4* r0 = (const float4*)(dc0 + row * B0);
        float4 p0 = __ldg(&r0[0]);
        float4 p1 = __ldg(&r0[1]);
        float v0[8] = {p0.x, p0.y, p0.z, p0.w, p1.x, p1.y, p1.z, p1.w};
        float c0 = v0[0];
#pragma unroll
        for (int k = 1; k < B0; k++)
            c0 *= (k <= a0) ? v0[k] : 1.0f;

        // c1 = within-group cumprod of dc1[row, a0*16 .. +16][a1]
        const float4* r1 = (const float4*)(dc1 + row * (B0 * B1) + a0 * B1);
        float4 q0 = __ldg(&r1[0]);
        float4 q1 = __ldg(&r1[1]);
        float4 q2 = __ldg(&r1[2]);
        float4 q3 = __ldg(&r1[3]);
        float v1[16] = {q0.x, q0.y, q0.z, q0.w, q1.x, q1.y, q1.z, q1.w,
                        q2.x, q2.y, q2.z, q2.w, q3.x, q3.y, q3.z, q3.w};
        float c1 = v1[0];
#pragma unroll
        for (int k = 1; k < B1; k++)
            c1 *= (k <= a1) ? v1[k] : 1.0f;

        pfx[idx] = c0 * c1;
    }
    __syncthreads();

    // ---------- Phase 2: scan + scale + store ----------
    float4*       dst = (float4*)out;
    const unsigned mask = 0xFFFFFFFFu;
    int c = tid & 3;                      // chunk-within-group (all iters)

#pragma unroll
    for (int it = 0; it < CPT; it++) {
        int chunk = tid + it * BLOCK;     // 0..2047 within the 4-row block
        int G = chunk >> 2;               // 0..511 -> pfx index

        float4 x = xs[it];
        float l0 = x.x;
        float l1 = l0 * x.y;
        float l2 = l1 * x.z;
        float l3 = l2 * x.w;

        // segmented inclusive scan of chunk totals across the 4-lane group
        float s = l3;
        float u = __shfl_up_sync(mask, s, 1);
        if (c >= 1) s *= u;
        u = __shfl_up_sync(mask, s, 2);
        if (c >= 2) s *= u;
        float e = __shfl_up_sync(mask, s, 1);   // exclusive prefix
        if (c == 0) e = 1.0f;

        float scale = pfx[G] * e;
        float4 o;
        o.x = l0 * scale;
        o.y = l1 * scale;
        o.z = l2 * scale;
        o.w = l3 * scale;
        __stcs(&dst[blk_base + chunk], o);
    }
}

extern "C" void kernel_launch(void* const* d_in, const int* in_sizes, int n_in,
                              void* d_out, int out_size) {
    const float* dc0 = (const float*)d_in[0];
    const float* dc1 = (const float*)d_in[1];
    const float* dc2 = (const float*)d_in[2];
    float* out = (float*)d_out;

    int batch = out_size / ROW_ELEMS;          // 32768 rows
    int blocks = batch / ROWS_PER_BLK;         // 8192 blocks
    det_prob_kernel<<<blocks, BLOCK>>>(dc0, dc1, dc2, out);
}

// round 8
// speedup vs baseline: 1.0198x; 1.0198x over previous
#include <cuda_runtime.h>
#include <cuda_bf16.h>

// DET_PROB hierarchical cumprod expansion — v6: warp-autonomous, no barrier.
// B0=8, B1=16, B2=16 -> 2048 leaves/row, 128 leaf-groups of 16.
//
// One warp owns 32 contiguous leaf groups (128 chunks, 1/4 of a row).
//  - Each lane front-batches 4 streaming float4 loads (MLP=4, .cs).
//  - Each lane computes ONE prefix (its group) into a register — latency
//    overlapped with the in-flight loads. No smem, no __syncthreads.
//  - Streaming loop fetches the right prefix via __shfl_sync and resolves
//    the within-group-of-16 cumprod with a 4-lane segmented shfl scan.

#define B0 8
#define B1 16
#define B2 16
#define GROUPS 128                 // leaf groups per row
#define ROW_ELEMS 2048
#define BLOCK 256                  // 8 warps
#define WARP_GROUPS 32             // groups per warp
#define WARP_CHUNKS 128            // float4 chunks per warp (4 iters x 32)

__global__ __launch_bounds__(BLOCK) void det_prob_kernel(
    const float* __restrict__ dc0,
    const float* __restrict__ dc1,
    const float* __restrict__ dc2,
    float* __restrict__ out)
{
    int tid  = threadIdx.x;
    int lane = tid & 31;
    size_t gwid = (size_t)blockIdx.x * (BLOCK / 32) + (tid >> 5);

    size_t chunk_base = gwid * WARP_CHUNKS;     // float4 units
    const float4* src = (const float4*)dc2;
    float4*       dst = (float4*)out;

    // ---------- Phase 0: front-batch 4 streaming loads ----------
    float4 x0 = __ldcs(&src[chunk_base + lane + 0 * 32]);
    float4 x1 = __ldcs(&src[chunk_base + lane + 1 * 32]);
    float4 x2 = __ldcs(&src[chunk_base + lane + 2 * 32]);
    float4 x3 = __ldcs(&src[chunk_base + lane + 3 * 32]);

    // ---------- Phase 1: one prefix per lane (overlaps loads) ----------
    // Warp's groups: [gwid*32, gwid*32+32) — always within one row.
    size_t gbase = gwid * WARP_GROUPS;
    size_t row   = gbase >> 7;
    int g  = (int)((gbase + lane) & 127);
    int a0 = g >> 4;
    int a1 = g & 15;

    float pfx;
    {
        // c0 = cumprod(dc0[row])[a0] — broadcast L1 hits
        const float4* r0 = (const float4*)(dc0 + row * B0);
        float4 p0 = __ldg(&r0[0]);
        float4 p1 = __ldg(&r0[1]);
        float v0[8] = {p0.x, p0.y, p0.z, p0.w, p1.x, p1.y, p1.z, p1.w};
        float c0 = v0[0];
#pragma unroll
        for (int k = 1; k < B0; k++)
            c0 *= (k <= a0) ? v0[k] : 1.0f;

        // c1 = within-group cumprod of dc1[row, a0*16 .. +16][a1]
        // Only 2 distinct a0 per warp -> 2 distinct 16B addresses per load.
        const float4* r1 = (const float4*)(dc1 + row * (B0 * B1) + a0 * B1);
        float4 q0 = __ldg(&r1[0]);
        float4 q1 = __ldg(&r1[1]);
        float4 q2 = __ldg(&r1[2]);
        float4 q3 = __ldg(&r1[3]);
        float v1[16] = {q0.x, q0.y, q0.z, q0.w, q1.x, q1.y, q1.z, q1.w,
                        q2.x, q2.y, q2.z, q2.w, q3.x, q3.y, q3.z, q3.w};
        float c1 = v1[0];
#pragma unroll
        for (int k = 1; k < B1; k++)
            c1 *= (k <= a1) ? v1[k] : 1.0f;

        pfx = c0 * c1;
    }

    // ---------- Phase 2: scan + scale + store (no barrier) ----------
    const unsigned mask = 0xFFFFFFFFu;
    int c = lane & 3;                 // chunk-within-group
    int gsel = lane >> 2;             // group slot 0..7 within this iter
    float4 xs[4] = {x0, x1, x2, x3};

#pragma unroll
    for (int it = 0; it < 4; it++) {
        float4 x = xs[it];
        float l0 = x.x;
        float l1 = l0 * x.y;
        float l2 = l1 * x.z;
        float l3 = l2 * x.w;

        // segmented inclusive scan of chunk totals across the 4-lane group
        float s = l3;
        float u = __shfl_up_sync(mask, s, 1);
        if (c >= 1) s *= u;
        u = __shfl_up_sync(mask, s, 2);
        if (c >= 2) s *= u;
        float e = __shfl_up_sync(mask, s, 1);   // exclusive prefix
        if (c == 0) e = 1.0f;

        // fetch this chunk's group prefix from the owning lane
        float pf = __shfl_sync(mask, pfx, it * 8 + gsel);

        float scale = pf * e;
        float4 o;
        o.x = l0 * scale;
        o.y = l1 * scale;
        o.z = l2 * scale;
        o.w = l3 * scale;
        __stcs(&dst[chunk_base + lane + it * 32], o);
    }
}

extern "C" void kernel_launch(void* const* d_in, const int* in_sizes, int n_in,
                              void* d_out, int out_size) {
    const float* dc0 = (const float*)d_in[0];
    const float* dc1 = (const float*)d_in[1];
    const float* dc2 = (const float*)d_in[2];
    float* out = (float*)d_out;

    int batch = out_size / ROW_ELEMS;               // 32768 rows
    // 4 warps per row, 8 warps per block -> batch/2 blocks
    int blocks = batch / 2;                         // 16384
    det_prob_kernel<<<blocks, BLOCK>>>(dc0, dc1, dc2, out);
}